// round 15
// baseline (speedup 1.0000x reference)
#include <cuda_runtime.h>
#include <math.h>

// ---------------------------------------------------------------------------
// EDR loss pipeline (round 14 = R10 baseline + stage2 j-split across 2 threads):
//   pack fused into IFFT stage1 -> complex IFFT(48000) = 48 (=8x6 regs) x 1000 (=10^3 smem)
//   -> Hann STFT via 2-pass radix-16 FFT-256 (8 frames/CTA, 2 barriers)
//   -> power -> suffix-sum over frames -> 10*log10 -> sum|dt-da| / sum|dt|
// ---------------------------------------------------------------------------

#define NSIG     256
#define NHALF    48000
#define ROWLEN   96000
#define TFRAMES  374
#define FBINS    257

// scratch (allowed: __device__ globals)
__device__ float2 g_bufA[NSIG * NHALF];              // y (time domain packed)
__device__ float2 g_bufB[NSIG * NHALF];              // stage-1 intermediate
__device__ float  g_P[NSIG * TFRAMES * FBINS];
__device__ float  g_partial[256];

// twiddle tables
__device__ float2 g_twpack[48000];    // e^{+2pi i k/96000}
__device__ float2 g_tw1000[1000];     // e^{+2pi i t/1000}
__device__ float2 g_tw48[48];         // e^{+2pi i t/48}
__device__ float2 g_tw10[10];         // e^{+2pi i t/10}
__device__ float2 g_tw256f[256];      // e^{-2pi i t/256}
__device__ float2 g_tw512[256];       // e^{-2pi i f/512}
__device__ float2 g_hann2[256];       // (hann(2i), hann(2i+1)), periodic Hann 512

__device__ __forceinline__ void cmac(float2& acc, float2 a, float2 w) {
    acc.x += a.x * w.x - a.y * w.y;
    acc.y += a.x * w.y + a.y * w.x;
}
__device__ __forceinline__ float2 cadd(float2 a, float2 b){ return make_float2(a.x+b.x, a.y+b.y); }
__device__ __forceinline__ float2 csub(float2 a, float2 b){ return make_float2(a.x-b.x, a.y-b.y); }
__device__ __forceinline__ float2 cmul(float2 a, float2 b){
    return make_float2(a.x*b.x - a.y*b.y, a.x*b.y + a.y*b.x);
}
__device__ __forceinline__ float2 cmuli(float2 a){ return make_float2(-a.y, a.x); }   // +i*a
__device__ __forceinline__ float2 cmulni(float2 a){ return make_float2(a.y, -a.x); }  // -i*a

// ---------------------------------------------------------------------------
__global__ void __launch_bounds__(512) k_setup() {
    int t = blockIdx.x * 512 + threadIdx.x;
    float s, c;
    if (t < 48000) {
        sincosf((float)t * 6.5449846949787352e-5f, &s, &c);   // +2pi/96000
        g_twpack[t] = make_float2(c, s);
    }
    if (t < 1000) {
        sincosf((float)t * 6.2831853071795865e-3f, &s, &c);   // +2pi/1000
        g_tw1000[t] = make_float2(c, s);
    }
    if (t < 48) {
        sincosf((float)t * 0.13089969389957472f, &s, &c);     // +2pi/48
        g_tw48[t] = make_float2(c, s);
    }
    if (t < 10) {
        sincosf((float)t * 0.62831853071795865f, &s, &c);     // +2pi/10
        g_tw10[t] = make_float2(c, s);
    }
    if (t < 256) {
        sincosf(-(float)t * 2.4543692606170259e-2f, &s, &c);  // -2pi/256
        g_tw256f[t] = make_float2(c, s);
        sincosf(-(float)t * 1.2271846303085130e-2f, &s, &c);  // -2pi/512
        g_tw512[t] = make_float2(c, s);
        float w0 = 0.5f - 0.5f * cosf((float)(2 * t)     * 1.2271846303085130e-2f);
        float w1 = 0.5f - 0.5f * cosf((float)(2 * t + 1) * 1.2271846303085130e-2f);
        g_hann2[t] = make_float2(w0, w1);
    }
}

// ---------------------------------------------------------------------------
// K2: fused pack + stage 1 of IFFT-48000 (byte-identical to the 334.6 baseline).
// ---------------------------------------------------------------------------
__global__ void __launch_bounds__(125) k_stage1(const float* __restrict__ tre,
                                                const float* __restrict__ tim,
                                                const float* __restrict__ are,
                                                const float* __restrict__ aim) {
    __shared__ float2 sW[48];
    int tid = threadIdx.x;               // 0..124
    int sig = blockIdx.y;
    int k2  = blockIdx.x * 125 + tid;    // 8 blocks * 125 = 1000

    if (tid < 48) sW[tid] = g_tw48[tid];
    __syncthreads();

    const float* re = (sig < 128 ? tre : are) + (size_t)(sig & 127) * ROWLEN;
    const float* im = (sig < 128 ? tim : aim) + (size_t)(sig & 127) * ROWLEN;

    float2 v[48];
#pragma unroll
    for (int k1 = 0; k1 < 48; k1++) {
        int k = k2 + 1000 * k1;
        float ar = __ldg(&re[k]),          ai = __ldg(&im[k]);
        float br = __ldg(&re[NHALF - k]),  bi = -__ldg(&im[NHALF - k]);
        float Ex = 0.5f * (ar + br), Ey = 0.5f * (ai + bi);
        float Dx = 0.5f * (ar - br), Dy = 0.5f * (ai - bi);
        float2 w = __ldg(&g_twpack[k]);                      // e^{+2pi i k/96000}
        float Ox = w.x * Dx - w.y * Dy;
        float Oy = w.x * Dy + w.y * Dx;
        v[k1] = make_float2(Ex - Oy, Ey + Ox);
    }
    if (k2 == 0) {                        // k==0 special case (k1=0 only)
        float r0 = __ldg(&re[0]), rM = __ldg(&re[NHALF]);
        v[0] = make_float2(0.5f * (r0 + rM), 0.5f * (r0 - rM));
    }

    // six DFT-8s (positive exponent), in place: v[6r+b] = F_b[r]
    const float C = 0.70710678118654752f;
#pragma unroll
    for (int b = 0; b < 6; b++) {
        float2 x0 = v[b],      x1 = v[b + 6],  x2 = v[b + 12], x3 = v[b + 18];
        float2 x4 = v[b + 24], x5 = v[b + 30], x6 = v[b + 36], x7 = v[b + 42];
        float2 g0 = cadd(x0, x4), g1 = csub(x0, x4);
        float2 g2 = cadd(x2, x6), g3 = csub(x2, x6);
        float2 h0 = cadd(x1, x5), h1 = csub(x1, x5);
        float2 h2 = cadd(x3, x7), h3 = csub(x3, x7);
        float2 ig3 = cmuli(g3), ih3 = cmuli(h3);
        float2 E0 = cadd(g0, g2), E2 = csub(g0, g2);
        float2 E1 = cadd(g1, ig3), E3 = csub(g1, ig3);
        float2 O0 = cadd(h0, h2), O2 = csub(h0, h2);
        float2 O1 = cadd(h1, ih3), O3 = csub(h1, ih3);
        float2 W1O1 = make_float2(C * (O1.x - O1.y),  C * (O1.x + O1.y));   // e^{+i pi/4}  * O1
        float2 W3O3 = make_float2(-C * (O3.x + O3.y), C * (O3.x - O3.y));   // e^{+i 3pi/4} * O3
        float2 iO2  = cmuli(O2);
        v[b]      = cadd(E0, O0);
        v[b + 6]  = cadd(E1, W1O1);
        v[b + 12] = cadd(E2, iO2);
        v[b + 18] = cadd(E3, W3O3);
        v[b + 24] = csub(E0, O0);
        v[b + 30] = csub(E1, W1O1);
        v[b + 36] = csub(E2, iO2);
        v[b + 42] = csub(E3, W3O3);
    }

    // per-thread twiddle recurrence: w_m = (1/48000) * e^{+2pi i k2 m/48000}
    float sn, cs;
    sincosf((float)k2 * 1.3089969389957471e-4f, &sn, &cs);
    float2 wstep = make_float2(cs, sn);
    float2 w = make_float2(1.0f / 48000.0f, 0.0f);

    float2* dstBase = g_bufB + (size_t)sig * NHALF;
#pragma unroll
    for (int m = 0; m < 48; m++) {
        int r6 = 6 * (m & 7);
        float2 acc = v[r6];
#pragma unroll
        for (int b = 1; b < 6; b++)
            cmac(acc, v[r6 + b], sW[(b * m) % 48]);
        dstBase[m * 1000 + k2] = cmul(acc, w);
        w = cmul(w, wstep);
    }
}

// ---------------------------------------------------------------------------
// stage-2 half-butterfly: thread owns outputs j = JB..JB+4 of one radix-10
// group g. Streams the 10 inputs, accumulates into acc[5] (compile-time sW10
// indices), applies output twiddle chain w0 * wstep^jj, writes dst with the
// pass's stride. Used with JB=0 (tid<128) and JB=5 (tid>=128): warp-uniform.
// ---------------------------------------------------------------------------
template<int JB>
__device__ __forceinline__ void do_pass(const float2* __restrict__ srcbuf, int g,
                                        const float2* __restrict__ sW10,
                                        float2* __restrict__ dstbuf,
                                        int base, int stride,
                                        float2 w0, float2 wstep) {
    float2 acc[5];
    float2 x = srcbuf[g];
#pragma unroll
    for (int jj = 0; jj < 5; jj++) acc[jj] = x;          // r=0: w10^0 = 1
#pragma unroll
    for (int r = 1; r < 10; r++) {
        x = srcbuf[g + 100 * r];
#pragma unroll
        for (int jj = 0; jj < 5; jj++)
            cmac(acc[jj], x, sW10[(r * (JB + jj)) % 10]);
    }
    float2 w = w0;
#pragma unroll
    for (int jj = 0; jj < 5; jj++) {
        dstbuf[base + stride * (JB + jj)] = cmul(acc[jj], w);
        w = cmul(w, wstep);
    }
}

// ---------------------------------------------------------------------------
// K3: stage 2 — 1000-point inverse DFT per (sig,m1) row, 3-pass radix-10
// Stockham (sign +). 256-thread CTA; 200 active threads, each owning half a
// butterfly (5 outputs). Half-start twiddles w^JB from exact table lookups.
// ---------------------------------------------------------------------------
__global__ void __launch_bounds__(256) k_stage2() {
    __shared__ float2 sA[1000];
    __shared__ float2 sB[1000];
    __shared__ float2 sW10[10];
    int tid = threadIdx.x;
    int m1  = blockIdx.x;   // 0..47
    int sig = blockIdx.y;   // 0..255

    if (tid < 10) sW10[tid] = g_tw10[tid];

    const float2* src = g_bufB + ((size_t)sig * 48 + m1) * 1000;
    for (int i = tid; i < 1000; i += 256) sA[i] = __ldg(&src[i]);   // coalesced stage

    int g   = tid & 127;            // group 0..99 (per half)
    bool act = (g < 100);
    bool lo  = (tid < 128);         // JB = 0 half (warp-uniform)
    int p1  = g / 10;
    const float2 ONE = make_float2(1.f, 0.f);

    float2 wg = ONE, wp = ONE, wg5 = ONE, wp5 = ONE;
    if (act) {
        wg = __ldg(&g_tw1000[g]);                  // e^{+2pi i g/1000}
        wp = __ldg(&g_tw1000[10 * p1]);            // e^{+2pi i p1/100}
        if (!lo) {
            wg5 = __ldg(&g_tw1000[(5 * g) % 1000]);   // wg^5 (exact)
            wp5 = __ldg(&g_tw1000[50 * p1]);          // wp^5 (exact, <=450)
        }
    }
    __syncthreads();

    // ---- pass 0: nn=1000, p=g: out[10g+j] = wg^j * sum_r sA[g+100r] w10^{rj}
    if (act) {
        if (lo) do_pass<0>(sA, g, sW10, sB, 10 * g, 1, ONE, wg);
        else    do_pass<5>(sA, g, sW10, sB, 10 * g, 1, wg5, wg);
    }
    __syncthreads();

    // ---- pass 1: nn=100, p=p1: out[g + 90 p1 + 10j] = wp^j * X[j]
    if (act) {
        if (lo) do_pass<0>(sB, g, sW10, sA, g + 90 * p1, 10, ONE, wp);
        else    do_pass<5>(sB, g, sW10, sA, g + 90 * p1, 10, wp5, wp);
    }
    __syncthreads();

    // ---- pass 2: nn=10, p=0: out[g + 100j], no twiddle; straight to gmem
    if (act) {
        float2* dst = g_bufA + (size_t)sig * NHALF + m1;   // y[m1 + 48*m2]
        if (lo) do_pass<0>(sA, g, sW10, dst, 48 * g, 4800, ONE, ONE);
        else    do_pass<5>(sA, g, sW10, dst, 48 * g, 4800, ONE, ONE);
    }
}

// ---------------------------------------------------------------------------
// Register DFT-16 (forward, sign -), natural order, 4x4 CT, const twiddles.
// ---------------------------------------------------------------------------
__device__ __forceinline__ void dft16(float2* v) {
    const float C1 = 0.92387953251128675613f;   // cos(pi/8)
    const float S1 = 0.38268343236508977173f;   // sin(pi/8)
    const float R  = 0.70710678118654752440f;   // sqrt(2)/2
    float2 T[16];
#pragma unroll
    for (int m1 = 0; m1 < 4; m1++) {
        float2 a = v[m1], b = v[m1 + 4], c = v[m1 + 8], d = v[m1 + 12];
        float2 s0 = cadd(a, c), s1 = csub(a, c);
        float2 s2 = cadd(b, d), s3 = csub(b, d);
        T[4 * m1 + 0] = cadd(s0, s2);
        T[4 * m1 + 1] = cadd(s1, cmulni(s3));
        T[4 * m1 + 2] = csub(s0, s2);
        T[4 * m1 + 3] = csub(s1, cmulni(s3));
    }
    T[5]  = cmul(T[5],  make_float2( C1, -S1));
    T[6]  = cmul(T[6],  make_float2(  R,  -R));
    T[7]  = cmul(T[7],  make_float2( S1, -C1));
    T[9]  = cmul(T[9],  make_float2(  R,  -R));
    T[10] = cmulni(T[10]);
    T[11] = cmul(T[11], make_float2( -R,  -R));
    T[13] = cmul(T[13], make_float2( S1, -C1));
    T[14] = cmul(T[14], make_float2( -R,  -R));
    T[15] = cmul(T[15], make_float2(-C1,  S1));
#pragma unroll
    for (int j2 = 0; j2 < 4; j2++) {
        float2 a = T[j2], b = T[4 + j2], c = T[8 + j2], d = T[12 + j2];
        float2 s0 = cadd(a, c), s1 = csub(a, c);
        float2 s2 = cadd(b, d), s3 = csub(b, d);
        v[j2]      = cadd(s0, s2);
        v[4 + j2]  = cadd(s1, cmulni(s3));
        v[8 + j2]  = csub(s0, s2);
        v[12 + j2] = csub(s1, cmulni(s3));
    }
}

// ---------------------------------------------------------------------------
// K4: STFT frame power via 2-pass radix-16 FFT-256 (byte-identical, 59us).
// ---------------------------------------------------------------------------
__global__ void __launch_bounds__(128) k_stft() {
    __shared__ float2 sMid[8][272];   // [n1*17 + k2], padded
    __shared__ float2 sOut[8][256];   // X natural order
    int tid = threadIdx.x;
    int lf  = tid >> 4;               // local frame 0..7
    int i   = tid & 15;               // n1 (pass0) / k2 (pass1)
    int fr  = blockIdx.x * 8 + lf;
    int sig = blockIdx.y;
    bool ok = fr < TFRAMES;

    float2 v[16];
    if (ok) {
        const float2* src = g_bufA + (size_t)sig * NHALF + 128 * fr;
#pragma unroll
        for (int n2 = 0; n2 < 16; n2++) {
            int idx = i + 16 * n2;
            float2 y = __ldg(&src[idx]);
            float2 h = __ldg(&g_hann2[idx]);
            v[n2] = make_float2(y.x * h.x, y.y * h.y);
        }
        dft16(v);                                   // v[k2] = A[k2]
        float2 wb = __ldg(&g_tw256f[i]);            // e^{-2pi i n1/256}
        float2 w = make_float2(1.f, 0.f);
        sMid[lf][i * 17] = v[0];
#pragma unroll
        for (int k2 = 1; k2 < 16; k2++) {
            w = cmul(w, wb);
            sMid[lf][i * 17 + k2] = cmul(v[k2], w);
        }
    }
    __syncthreads();

    if (ok) {
#pragma unroll
        for (int n1 = 0; n1 < 16; n1++) v[n1] = sMid[lf][n1 * 17 + i];
        dft16(v);                                   // v[k1] = X[16k1 + i]
#pragma unroll
        for (int k1 = 0; k1 < 16; k1++) sOut[lf][16 * k1 + i] = v[k1];
    }
    __syncthreads();

    if (ok) {
        float* Pout = g_P + ((size_t)sig * TFRAMES + fr) * FBINS;
#pragma unroll
        for (int h = 0; h < 16; h++) {
            int f = i + 16 * h;
            float2 z1 = sOut[lf][f];
            float2 z2 = sOut[lf][(256 - f) & 255]; z2.y = -z2.y;
            float Ex = 0.5f * (z1.x + z2.x), Ey = 0.5f * (z1.y + z2.y);
            float Dx = 0.5f * (z1.x - z2.x), Dy = 0.5f * (z1.y - z2.y);
            float Ox = Dy, Oy = -Dx;                     // O = D / i
            float2 tw = __ldg(&g_tw512[f]);              // e^{-2pi i f/512}
            float Sx = Ex + Ox * tw.x - Oy * tw.y;
            float Sy = Ey + Ox * tw.y + Oy * tw.x;
            Pout[f] = Sx * Sx + Sy * Sy;
        }
        if (i == 0) {
            float nv = sOut[lf][0].x - sOut[lf][0].y;    // Nyquist: E[0]-O[0]
            Pout[256] = nv * nv;
        }
    }
}

// ---------------------------------------------------------------------------
// K5: per-pair EDR + loss partials (byte-identical to baseline).
// ---------------------------------------------------------------------------
__global__ void __launch_bounds__(512) k_loss() {
    __shared__ float sn[512], sd[512];
    int tid = threadIdx.x;
    int s   = blockIdx.x;                       // 0..127
    const float K = 3.0102999566398120f;        // 10 / log2(10)
    float num = 0.f, den = 0.f;
    if (tid < FBINS) {
        const float* pt = g_P + (size_t)s * TFRAMES * FBINS + tid;
        const float* pa = g_P + (size_t)(s + 128) * TFRAMES * FBINS + tid;
        float st = 0.f, sv = 0.f;
        for (int t = TFRAMES - 1; t >= 0; --t) {
            st += pt[t * FBINS];
            sv += pa[t * FBINS];
            float et = K * __log2f(st);
            float ea = K * __log2f(sv);
            num += fabsf(et - ea);
            den += fabsf(et);
        }
    }
    sn[tid] = num; sd[tid] = den;
    __syncthreads();
    for (int off = 256; off > 0; off >>= 1) {
        if (tid < off) { sn[tid] += sn[tid + off]; sd[tid] += sd[tid + off]; }
        __syncthreads();
    }
    if (tid == 0) {
        g_partial[2 * s]     = sn[0];
        g_partial[2 * s + 1] = sd[0];
    }
}

__global__ void k_final(float* __restrict__ out) {
    double n = 0.0, d = 0.0;
    for (int i = 0; i < 128; i++) {
        n += (double)g_partial[2 * i];
        d += (double)g_partial[2 * i + 1];
    }
    out[0] = (float)(n / d);
}

// ---------------------------------------------------------------------------
extern "C" void kernel_launch(void* const* d_in, const int* in_sizes, int n_in,
                              void* d_out, int out_size) {
    const float* tre = (const float*)d_in[0];
    const float* tim = (const float*)d_in[1];
    const float* are = (const float*)d_in[2];
    const float* aim = (const float*)d_in[3];

    k_setup <<<94, 512>>>();
    k_stage1<<<dim3(8,  NSIG), 125>>>(tre, tim, are, aim);
    k_stage2<<<dim3(48, NSIG), 256>>>();
    k_stft  <<<dim3(47, NSIG), 128>>>();
    k_loss  <<<128, 512>>>();
    k_final <<<1, 1>>>((float*)d_out);
}

// round 17
// speedup vs baseline: 1.0562x; 1.0562x over previous
#include <cuda_runtime.h>
#include <cuda_bf16.h>
#include <math.h>

// ---------------------------------------------------------------------------
// EDR loss pipeline (round 15 = measured-best baseline + g_P stored as bf16):
//   pack fused into IFFT stage1 -> complex IFFT(48000) = 48 (=8x6 regs) x 1000 (=10^3 smem)
//   -> Hann STFT via 2-pass radix-16 FFT-256 (8 frames/CTA, 2 barriers)
//   -> power (bf16) -> suffix-sum over frames -> 10*log10 -> loss
// ---------------------------------------------------------------------------

#define NSIG     256
#define NHALF    48000
#define ROWLEN   96000
#define TFRAMES  374
#define FBINS    257

// scratch (allowed: __device__ globals)
__device__ float2 g_bufA[NSIG * NHALF];              // y (time domain packed)
__device__ float2 g_bufB[NSIG * NHALF];              // stage-1 intermediate
__device__ __nv_bfloat16 g_P[NSIG * TFRAMES * FBINS];  // |STFT|^2, bf16 (range-safe)
__device__ float  g_partial[256];

// twiddle tables
__device__ float2 g_twpack[48000];    // e^{+2pi i k/96000}
__device__ float2 g_tw1000[1000];     // e^{+2pi i t/1000}
__device__ float2 g_tw48[48];         // e^{+2pi i t/48}
__device__ float2 g_tw10[10];         // e^{+2pi i t/10}
__device__ float2 g_tw256f[256];      // e^{-2pi i t/256}
__device__ float2 g_tw512[256];       // e^{-2pi i f/512}
__device__ float2 g_hann2[256];       // (hann(2i), hann(2i+1)), periodic Hann 512

__device__ __forceinline__ void cmac(float2& acc, float2 a, float2 w) {
    acc.x += a.x * w.x - a.y * w.y;
    acc.y += a.x * w.y + a.y * w.x;
}
__device__ __forceinline__ float2 cadd(float2 a, float2 b){ return make_float2(a.x+b.x, a.y+b.y); }
__device__ __forceinline__ float2 csub(float2 a, float2 b){ return make_float2(a.x-b.x, a.y-b.y); }
__device__ __forceinline__ float2 cmul(float2 a, float2 b){
    return make_float2(a.x*b.x - a.y*b.y, a.x*b.y + a.y*b.x);
}
__device__ __forceinline__ float2 cmuli(float2 a){ return make_float2(-a.y, a.x); }   // +i*a
__device__ __forceinline__ float2 cmulni(float2 a){ return make_float2(a.y, -a.x); }  // -i*a

// ---------------------------------------------------------------------------
__global__ void __launch_bounds__(512) k_setup() {
    int t = blockIdx.x * 512 + threadIdx.x;
    float s, c;
    if (t < 48000) {
        sincosf((float)t * 6.5449846949787352e-5f, &s, &c);   // +2pi/96000
        g_twpack[t] = make_float2(c, s);
    }
    if (t < 1000) {
        sincosf((float)t * 6.2831853071795865e-3f, &s, &c);   // +2pi/1000
        g_tw1000[t] = make_float2(c, s);
    }
    if (t < 48) {
        sincosf((float)t * 0.13089969389957472f, &s, &c);     // +2pi/48
        g_tw48[t] = make_float2(c, s);
    }
    if (t < 10) {
        sincosf((float)t * 0.62831853071795865f, &s, &c);     // +2pi/10
        g_tw10[t] = make_float2(c, s);
    }
    if (t < 256) {
        sincosf(-(float)t * 2.4543692606170259e-2f, &s, &c);  // -2pi/256
        g_tw256f[t] = make_float2(c, s);
        sincosf(-(float)t * 1.2271846303085130e-2f, &s, &c);  // -2pi/512
        g_tw512[t] = make_float2(c, s);
        float w0 = 0.5f - 0.5f * cosf((float)(2 * t)     * 1.2271846303085130e-2f);
        float w1 = 0.5f - 0.5f * cosf((float)(2 * t + 1) * 1.2271846303085130e-2f);
        g_hann2[t] = make_float2(w0, w1);
    }
}

// ---------------------------------------------------------------------------
// K2: fused pack + stage 1 of IFFT-48000 (byte-identical to baseline).
// ---------------------------------------------------------------------------
__global__ void __launch_bounds__(125) k_stage1(const float* __restrict__ tre,
                                                const float* __restrict__ tim,
                                                const float* __restrict__ are,
                                                const float* __restrict__ aim) {
    __shared__ float2 sW[48];
    int tid = threadIdx.x;               // 0..124
    int sig = blockIdx.y;
    int k2  = blockIdx.x * 125 + tid;    // 8 blocks * 125 = 1000

    if (tid < 48) sW[tid] = g_tw48[tid];
    __syncthreads();

    const float* re = (sig < 128 ? tre : are) + (size_t)(sig & 127) * ROWLEN;
    const float* im = (sig < 128 ? tim : aim) + (size_t)(sig & 127) * ROWLEN;

    float2 v[48];
#pragma unroll
    for (int k1 = 0; k1 < 48; k1++) {
        int k = k2 + 1000 * k1;
        float ar = __ldg(&re[k]),          ai = __ldg(&im[k]);
        float br = __ldg(&re[NHALF - k]),  bi = -__ldg(&im[NHALF - k]);
        float Ex = 0.5f * (ar + br), Ey = 0.5f * (ai + bi);
        float Dx = 0.5f * (ar - br), Dy = 0.5f * (ai - bi);
        float2 w = __ldg(&g_twpack[k]);                      // e^{+2pi i k/96000}
        float Ox = w.x * Dx - w.y * Dy;
        float Oy = w.x * Dy + w.y * Dx;
        v[k1] = make_float2(Ex - Oy, Ey + Ox);
    }
    if (k2 == 0) {                        // k==0 special case (k1=0 only)
        float r0 = __ldg(&re[0]), rM = __ldg(&re[NHALF]);
        v[0] = make_float2(0.5f * (r0 + rM), 0.5f * (r0 - rM));
    }

    // six DFT-8s (positive exponent), in place: v[6r+b] = F_b[r]
    const float C = 0.70710678118654752f;
#pragma unroll
    for (int b = 0; b < 6; b++) {
        float2 x0 = v[b],      x1 = v[b + 6],  x2 = v[b + 12], x3 = v[b + 18];
        float2 x4 = v[b + 24], x5 = v[b + 30], x6 = v[b + 36], x7 = v[b + 42];
        float2 g0 = cadd(x0, x4), g1 = csub(x0, x4);
        float2 g2 = cadd(x2, x6), g3 = csub(x2, x6);
        float2 h0 = cadd(x1, x5), h1 = csub(x1, x5);
        float2 h2 = cadd(x3, x7), h3 = csub(x3, x7);
        float2 ig3 = cmuli(g3), ih3 = cmuli(h3);
        float2 E0 = cadd(g0, g2), E2 = csub(g0, g2);
        float2 E1 = cadd(g1, ig3), E3 = csub(g1, ig3);
        float2 O0 = cadd(h0, h2), O2 = csub(h0, h2);
        float2 O1 = cadd(h1, ih3), O3 = csub(h1, ih3);
        float2 W1O1 = make_float2(C * (O1.x - O1.y),  C * (O1.x + O1.y));   // e^{+i pi/4}  * O1
        float2 W3O3 = make_float2(-C * (O3.x + O3.y), C * (O3.x - O3.y));   // e^{+i 3pi/4} * O3
        float2 iO2  = cmuli(O2);
        v[b]      = cadd(E0, O0);
        v[b + 6]  = cadd(E1, W1O1);
        v[b + 12] = cadd(E2, iO2);
        v[b + 18] = cadd(E3, W3O3);
        v[b + 24] = csub(E0, O0);
        v[b + 30] = csub(E1, W1O1);
        v[b + 36] = csub(E2, iO2);
        v[b + 42] = csub(E3, W3O3);
    }

    // per-thread twiddle recurrence: w_m = (1/48000) * e^{+2pi i k2 m/48000}
    float sn, cs;
    sincosf((float)k2 * 1.3089969389957471e-4f, &sn, &cs);
    float2 wstep = make_float2(cs, sn);
    float2 w = make_float2(1.0f / 48000.0f, 0.0f);

    float2* dstBase = g_bufB + (size_t)sig * NHALF;
#pragma unroll
    for (int m = 0; m < 48; m++) {
        int r6 = 6 * (m & 7);
        float2 acc = v[r6];
#pragma unroll
        for (int b = 1; b < 6; b++)
            cmac(acc, v[r6 + b], sW[(b * m) % 48]);
        dstBase[m * 1000 + k2] = cmul(acc, w);
        w = cmul(w, wstep);
    }
}

// ---------------------------------------------------------------------------
// K3: stage 2 — 1000-point inverse DFT per (sig,m1) row, 3-pass radix-10
// Stockham (sign +), streaming accumulators (exact R10-passing version).
// ---------------------------------------------------------------------------
__global__ void __launch_bounds__(128) k_stage2() {
    __shared__ float2 sA[1000];
    __shared__ float2 sB[1000];
    __shared__ float2 sW10[10];
    int tid = threadIdx.x;
    int m1  = blockIdx.x;   // 0..47
    int sig = blockIdx.y;   // 0..255

    if (tid < 10) sW10[tid] = g_tw10[tid];

    const float2* src = g_bufB + ((size_t)sig * 48 + m1) * 1000;
    for (int i = tid; i < 1000; i += 128) sA[i] = __ldg(&src[i]);   // coalesced stage

    bool act = (tid < 100);
    int g = tid;
    int p1 = g / 10;
    float2 wg = make_float2(1.f, 0.f), wp = make_float2(1.f, 0.f);
    if (act) {
        wg = __ldg(&g_tw1000[g]);          // e^{+2pi i g/1000}
        wp = __ldg(&g_tw1000[10 * p1]);    // e^{+2pi i p1/100}
    }
    __syncthreads();

    float2 acc[10];

    // ---- pass 0: nn=1000, p=g: out[10g+j] = wg^j * sum_r sA[g+100r] w10^{rj}
    if (act) {
        float2 x = sA[g];
#pragma unroll
        for (int j = 0; j < 10; j++) acc[j] = x;
#pragma unroll
        for (int r = 1; r < 10; r++) {
            x = sA[g + 100 * r];
#pragma unroll
            for (int j = 0; j < 10; j++) cmac(acc[j], x, sW10[(r * j) % 10]);
        }
        float2 w = make_float2(1.f, 0.f);
        sB[10 * g] = acc[0];
#pragma unroll
        for (int j = 1; j < 10; j++) {
            w = cmul(w, wg);
            sB[10 * g + j] = cmul(acc[j], w);
        }
    }
    __syncthreads();

    // ---- pass 1: nn=100, p=p1: out[g + 90 p1 + 10j], tw = wp^j
    if (act) {
        float2 x = sB[g];
#pragma unroll
        for (int j = 0; j < 10; j++) acc[j] = x;
#pragma unroll
        for (int r = 1; r < 10; r++) {
            x = sB[g + 100 * r];
#pragma unroll
            for (int j = 0; j < 10; j++) cmac(acc[j], x, sW10[(r * j) % 10]);
        }
        int ob = g + 90 * p1;
        float2 w = make_float2(1.f, 0.f);
        sA[ob] = acc[0];
#pragma unroll
        for (int j = 1; j < 10; j++) {
            w = cmul(w, wp);
            sA[ob + 10 * j] = cmul(acc[j], w);
        }
    }
    __syncthreads();

    // ---- pass 2: nn=10, p=0: out[g + 100j], no twiddle; straight to gmem
    if (act) {
        float2 x = sA[g];
#pragma unroll
        for (int j = 0; j < 10; j++) acc[j] = x;
#pragma unroll
        for (int r = 1; r < 10; r++) {
            x = sA[g + 100 * r];
#pragma unroll
            for (int j = 0; j < 10; j++) cmac(acc[j], x, sW10[(r * j) % 10]);
        }
        float2* dst = g_bufA + (size_t)sig * NHALF + m1;   // y[m1 + 48*m2]
#pragma unroll
        for (int j = 0; j < 10; j++) dst[48 * (g + 100 * j)] = acc[j];
    }
}

// ---------------------------------------------------------------------------
// Register DFT-16 (forward, sign -), natural order, 4x4 CT, const twiddles.
// ---------------------------------------------------------------------------
__device__ __forceinline__ void dft16(float2* v) {
    const float C1 = 0.92387953251128675613f;   // cos(pi/8)
    const float S1 = 0.38268343236508977173f;   // sin(pi/8)
    const float R  = 0.70710678118654752440f;   // sqrt(2)/2
    float2 T[16];
#pragma unroll
    for (int m1 = 0; m1 < 4; m1++) {
        float2 a = v[m1], b = v[m1 + 4], c = v[m1 + 8], d = v[m1 + 12];
        float2 s0 = cadd(a, c), s1 = csub(a, c);
        float2 s2 = cadd(b, d), s3 = csub(b, d);
        T[4 * m1 + 0] = cadd(s0, s2);
        T[4 * m1 + 1] = cadd(s1, cmulni(s3));
        T[4 * m1 + 2] = csub(s0, s2);
        T[4 * m1 + 3] = csub(s1, cmulni(s3));
    }
    T[5]  = cmul(T[5],  make_float2( C1, -S1));
    T[6]  = cmul(T[6],  make_float2(  R,  -R));
    T[7]  = cmul(T[7],  make_float2( S1, -C1));
    T[9]  = cmul(T[9],  make_float2(  R,  -R));
    T[10] = cmulni(T[10]);
    T[11] = cmul(T[11], make_float2( -R,  -R));
    T[13] = cmul(T[13], make_float2( S1, -C1));
    T[14] = cmul(T[14], make_float2( -R,  -R));
    T[15] = cmul(T[15], make_float2(-C1,  S1));
#pragma unroll
    for (int j2 = 0; j2 < 4; j2++) {
        float2 a = T[j2], b = T[4 + j2], c = T[8 + j2], d = T[12 + j2];
        float2 s0 = cadd(a, c), s1 = csub(a, c);
        float2 s2 = cadd(b, d), s3 = csub(b, d);
        v[j2]      = cadd(s0, s2);
        v[4 + j2]  = cadd(s1, cmulni(s3));
        v[8 + j2]  = csub(s0, s2);
        v[12 + j2] = csub(s1, cmulni(s3));
    }
}

// ---------------------------------------------------------------------------
// K4: STFT frame power via 2-pass radix-16 FFT-256; P written as bf16.
// ---------------------------------------------------------------------------
__global__ void __launch_bounds__(128) k_stft() {
    __shared__ float2 sMid[8][272];   // [n1*17 + k2], padded
    __shared__ float2 sOut[8][256];   // X natural order
    int tid = threadIdx.x;
    int lf  = tid >> 4;               // local frame 0..7
    int i   = tid & 15;               // n1 (pass0) / k2 (pass1)
    int fr  = blockIdx.x * 8 + lf;
    int sig = blockIdx.y;
    bool ok = fr < TFRAMES;

    float2 v[16];
    if (ok) {
        const float2* src = g_bufA + (size_t)sig * NHALF + 128 * fr;
#pragma unroll
        for (int n2 = 0; n2 < 16; n2++) {
            int idx = i + 16 * n2;
            float2 y = __ldg(&src[idx]);
            float2 h = __ldg(&g_hann2[idx]);
            v[n2] = make_float2(y.x * h.x, y.y * h.y);
        }
        dft16(v);                                   // v[k2] = A[k2]
        float2 wb = __ldg(&g_tw256f[i]);            // e^{-2pi i n1/256}
        float2 w = make_float2(1.f, 0.f);
        sMid[lf][i * 17] = v[0];
#pragma unroll
        for (int k2 = 1; k2 < 16; k2++) {
            w = cmul(w, wb);
            sMid[lf][i * 17 + k2] = cmul(v[k2], w);
        }
    }
    __syncthreads();

    if (ok) {
#pragma unroll
        for (int n1 = 0; n1 < 16; n1++) v[n1] = sMid[lf][n1 * 17 + i];
        dft16(v);                                   // v[k1] = X[16k1 + i]
#pragma unroll
        for (int k1 = 0; k1 < 16; k1++) sOut[lf][16 * k1 + i] = v[k1];
    }
    __syncthreads();

    if (ok) {
        __nv_bfloat16* Pout = g_P + ((size_t)sig * TFRAMES + fr) * FBINS;
#pragma unroll
        for (int h = 0; h < 16; h++) {
            int f = i + 16 * h;
            float2 z1 = sOut[lf][f];
            float2 z2 = sOut[lf][(256 - f) & 255]; z2.y = -z2.y;
            float Ex = 0.5f * (z1.x + z2.x), Ey = 0.5f * (z1.y + z2.y);
            float Dx = 0.5f * (z1.x - z2.x), Dy = 0.5f * (z1.y - z2.y);
            float Ox = Dy, Oy = -Dx;                     // O = D / i
            float2 tw = __ldg(&g_tw512[f]);              // e^{-2pi i f/512}
            float Sx = Ex + Ox * tw.x - Oy * tw.y;
            float Sy = Ey + Ox * tw.y + Oy * tw.x;
            Pout[f] = __float2bfloat16(Sx * Sx + Sy * Sy);
        }
        if (i == 0) {
            float nv = sOut[lf][0].x - sOut[lf][0].y;    // Nyquist: E[0]-O[0]
            Pout[256] = __float2bfloat16(nv * nv);
        }
    }
}

// ---------------------------------------------------------------------------
// K5: per-pair EDR + loss partials (bf16 reads; sums/logs in fp32).
// ---------------------------------------------------------------------------
__global__ void __launch_bounds__(512) k_loss() {
    __shared__ float sn[512], sd[512];
    int tid = threadIdx.x;
    int s   = blockIdx.x;                       // 0..127
    const float K = 3.0102999566398120f;        // 10 / log2(10)
    float num = 0.f, den = 0.f;
    if (tid < FBINS) {
        const __nv_bfloat16* pt = g_P + (size_t)s * TFRAMES * FBINS + tid;
        const __nv_bfloat16* pa = g_P + (size_t)(s + 128) * TFRAMES * FBINS + tid;
        float st = 0.f, sv = 0.f;
        for (int t = TFRAMES - 1; t >= 0; --t) {
            st += __bfloat162float(pt[t * FBINS]);
            sv += __bfloat162float(pa[t * FBINS]);
            float et = K * __log2f(st);
            float ea = K * __log2f(sv);
            num += fabsf(et - ea);
            den += fabsf(et);
        }
    }
    sn[tid] = num; sd[tid] = den;
    __syncthreads();
    for (int off = 256; off > 0; off >>= 1) {
        if (tid < off) { sn[tid] += sn[tid + off]; sd[tid] += sd[tid + off]; }
        __syncthreads();
    }
    if (tid == 0) {
        g_partial[2 * s]     = sn[0];
        g_partial[2 * s + 1] = sd[0];
    }
}

__global__ void k_final(float* __restrict__ out) {
    double n = 0.0, d = 0.0;
    for (int i = 0; i < 128; i++) {
        n += (double)g_partial[2 * i];
        d += (double)g_partial[2 * i + 1];
    }
    out[0] = (float)(n / d);
}

// ---------------------------------------------------------------------------
extern "C" void kernel_launch(void* const* d_in, const int* in_sizes, int n_in,
                              void* d_out, int out_size) {
    const float* tre = (const float*)d_in[0];
    const float* tim = (const float*)d_in[1];
    const float* are = (const float*)d_in[2];
    const float* aim = (const float*)d_in[3];

    k_setup <<<94, 512>>>();
    k_stage1<<<dim3(8,  NSIG), 125>>>(tre, tim, are, aim);
    k_stage2<<<dim3(48, NSIG), 128>>>();
    k_stft  <<<dim3(47, NSIG), 128>>>();
    k_loss  <<<128, 512>>>();
    k_final <<<1, 1>>>((float*)d_out);
}